// round 2
// baseline (speedup 1.0000x reference)
#include <cuda_runtime.h>

#define A_N 5625
#define SORT_N 8192
#define M_TOT 1250
#define K_TOT 4608
#define N_TOT 512

// ---------------- scratch (device globals; no runtime allocation) ----------
__device__ float g_A[M_TOT * K_TOT];                 // im2col, 23 MB
__device__ float g_Bt[K_TOT * N_TOT];                // transposed weights, 9.4 MB
__device__ float g_h[M_TOT * N_TOT];                 // conv output (m, c), fp32
__device__ float4 g_boxes[2 * A_N];
__device__ float g_probs[2 * A_N];
__device__ unsigned long long g_keys[2 * A_N];

// ---------------- weight transpose: Bt[k][n] = w[n][k] ---------------------
__global__ void transpose_w(const float* __restrict__ w) {
    __shared__ float sh[32][33];
    int k0 = blockIdx.x * 32, n0 = blockIdx.y * 32;
    int tx = threadIdx.x, ty = threadIdx.y;
    sh[ty][tx] = w[(size_t)(n0 + ty) * K_TOT + k0 + tx];
    __syncthreads();
    g_Bt[(size_t)(k0 + ty) * N_TOT + n0 + tx] = sh[tx][ty];
}

// ---------------- im2col with SAME zero padding -----------------------------
__global__ void im2col_k(const float* __restrict__ x) {
    int e = blockIdx.x * 256 + threadIdx.x;
    if (e >= M_TOT * K_TOT) return;
    int m = e / K_TOT, k = e - m * K_TOT;
    int b = m / 625, p = m - b * 625;
    int y = p / 25, xx = p - y * 25;
    int ci = k / 9, r = k - ci * 9;
    int ky = r / 3, kx = r - ky * 3;
    int iy = y + ky - 1, ix = xx + kx - 1;
    float v = 0.f;
    if (iy >= 0 && iy < 25 && ix >= 0 && ix < 25)
        v = x[((size_t)(b * 512 + ci) * 25 + iy) * 25 + ix];
    g_A[e] = v;
}

// ---------------- GEMM, fp32 products + fp64 accumulation ------------------
// 64x64 CTA tile, 256 threads, 4x4 micro-tile of doubles.
__global__ void __launch_bounds__(256, 2) conv_gemm64(const float* __restrict__ conv_b) {
    __shared__ float As[16][68];   // transposed A chunk, padded
    __shared__ float Bs[16][64];
    int m0 = blockIdx.x * 64;
    int n0 = blockIdx.y * 64;
    int tid = threadIdx.x;
    int tr = tid >> 4, tc = tid & 15;

    double acc[4][4];
#pragma unroll
    for (int r = 0; r < 4; r++)
#pragma unroll
        for (int c = 0; c < 4; c++) acc[r][c] = 0.0;

    int ar = tid >> 2, aq = (tid & 3) * 4;   // A: 64 rows x 16 k
    int bk = tid >> 4, bn = (tid & 15) * 4;  // B: 16 k x 64 n

    const float* Ab = g_A + (size_t)m0 * K_TOT;
    const float* Bb = g_Bt + n0;
    bool arow_ok = (m0 + ar) < M_TOT;

    for (int k0 = 0; k0 < K_TOT; k0 += 16) {
        float4 ra = arow_ok ? *(const float4*)(Ab + (size_t)ar * K_TOT + k0 + aq)
                            : make_float4(0.f, 0.f, 0.f, 0.f);
        float4 rb = *(const float4*)(Bb + (size_t)(k0 + bk) * N_TOT + bn);
        __syncthreads();   // previous chunk fully consumed
        As[aq + 0][ar] = ra.x; As[aq + 1][ar] = ra.y;
        As[aq + 2][ar] = ra.z; As[aq + 3][ar] = ra.w;
        *(float4*)&Bs[bk][bn] = rb;
        __syncthreads();

#pragma unroll
        for (int ks = 0; ks < 16; ks++) {
            float4 a = *(float4*)&As[ks][tr * 4];
            float4 b = *(float4*)&Bs[ks][tc * 4];
            double ad[4] = {(double)a.x, (double)a.y, (double)a.z, (double)a.w};
            double bd[4] = {(double)b.x, (double)b.y, (double)b.z, (double)b.w};
#pragma unroll
            for (int r = 0; r < 4; r++)
#pragma unroll
                for (int c = 0; c < 4; c++) acc[r][c] += ad[r] * bd[c];
        }
    }

#pragma unroll
    for (int r = 0; r < 4; r++) {
        int m = m0 + tr * 4 + r;
        if (m < M_TOT) {
#pragma unroll
            for (int c = 0; c < 4; c++) {
                int n = n0 + tc * 4 + c;
                float v = (float)acc[r][c] + conv_b[n];
                g_h[(size_t)m * N_TOT + n] = fmaxf(v, 0.f);
            }
        }
    }
}

// ---------------- heads (36 reg + 9 cls), fp64 acc, + decode + sort key ----
__global__ void heads_decode(const float* __restrict__ reg_w, const float* __restrict__ reg_b,
                             const float* __restrict__ cls_w, const float* __restrict__ cls_b,
                             const float* __restrict__ anchors) {
    __shared__ float sh[512];
    __shared__ float so[45];
    int m = blockIdx.x;            // b*625 + p
    int tid = threadIdx.x;         // 128
    ((float4*)sh)[tid] = ((const float4*)(g_h + (size_t)m * 512))[tid];
    __syncthreads();
    if (tid < 45) {
        const float* w = (tid < 36) ? (reg_w + (size_t)tid * 512) : (cls_w + (size_t)(tid - 36) * 512);
        double acc = (double)((tid < 36) ? reg_b[tid] : cls_b[tid - 36]);
        const float4* w4 = (const float4*)w;
#pragma unroll 4
        for (int k = 0; k < 128; k++) {
            float4 a = ((const float4*)sh)[k];
            float4 bb = __ldg(w4 + k);
            acc += (double)a.x * (double)bb.x + (double)a.y * (double)bb.y
                 + (double)a.z * (double)bb.z + (double)a.w * (double)bb.w;
        }
        so[tid] = (float)acc;      // round to fp32 exactly once, like the reference
    }
    __syncthreads();
    if (tid < 9) {
        int b = m / 625, p = m - b * 625;
        int a = p * 9 + tid;
        float4 anc = ((const float4*)anchors)[a];
        float acx = (anc.x + anc.z) * 0.5f, acy = (anc.y + anc.w) * 0.5f;
        float aw = anc.z - anc.x, ah = anc.w - anc.y;
        float ox = so[tid * 4 + 0], oy = so[tid * 4 + 1];
        float ow = so[tid * 4 + 2], oh = so[tid * 4 + 3];
        float cx = ox * aw / 10.0f + acx;
        float cy = oy * ah / 10.0f + acy;
        float bw = expf(ow / 5.0f) * aw;
        float bh = expf(oh / 5.0f) * ah;
        float4 box = make_float4(cx - bw * 0.5f, cy - bh * 0.5f, cx + bw * 0.5f, cy + bh * 0.5f);
        float logit = so[36 + tid];
        float prob = 1.0f / (1.0f + expf(-logit));
        int gi = b * A_N + a;
        g_boxes[gi] = box;
        g_probs[gi] = prob;
        float keyf = (prob > 0.5f) ? prob : -1.0f;
        unsigned u = __float_as_uint(keyf);
        u = (u & 0x80000000u) ? ~u : (u | 0x80000000u);   // monotone ascending map
        g_keys[gi] = ((unsigned long long)(~u) << 32) | (unsigned)a;  // ascending => desc key, stable
    }
}

// ---------------- per-image stable sort + greedy NMS -----------------------
// dyn shared: u64 arr[8192] | float4 sbox[5632] | float sarea[5632] | u32 sup[192]
#define SMEM_ARR   0
#define SMEM_BOX   65536
#define SMEM_AREA  (65536 + 90112)
#define SMEM_SUP   (65536 + 90112 + 22528)
#define SMEM_NMS_BYTES (SMEM_SUP + 192 * 4)

__global__ void __launch_bounds__(1024) sort_nms(float* __restrict__ out) {
    extern __shared__ unsigned char smem_raw[];
    unsigned long long* arr = (unsigned long long*)(smem_raw + SMEM_ARR);
    float4* sbox = (float4*)(smem_raw + SMEM_BOX);
    float* sarea = (float*)(smem_raw + SMEM_AREA);
    unsigned* sup = (unsigned*)(smem_raw + SMEM_SUP);
    __shared__ int s_cur;

    int b = blockIdx.x;
    int tid = threadIdx.x;

    for (int i = tid; i < SORT_N; i += 1024)
        arr[i] = (i < A_N) ? g_keys[b * A_N + i] : 0xFFFFFFFFFFFFFFFFull;
    if (tid < 192) sup[tid] = 0u;
    if (tid == 0) s_cur = -1;
    __syncthreads();

    // bitonic sort, ascending
    for (int k = 2; k <= SORT_N; k <<= 1) {
        for (int j = k >> 1; j > 0; j >>= 1) {
            for (int i = tid; i < SORT_N; i += 1024) {
                int ixj = i ^ j;
                if (ixj > i) {
                    unsigned long long u = arr[i], v = arr[ixj];
                    bool up = (i & k) == 0;
                    if ((u > v) == up) { arr[i] = v; arr[ixj] = u; }
                }
            }
            __syncthreads();
        }
    }

    // gather sorted boxes/probs, write cols 0..4, init suppression = !valid
    for (int i = tid; i < A_N; i += 1024) {
        unsigned idx = (unsigned)(arr[i] & 0xFFFFFFFFu);
        float4 bx = g_boxes[b * A_N + idx];
        float p = g_probs[b * A_N + idx];
        sbox[i] = bx;
        sarea[i] = (bx.z - bx.x) * (bx.w - bx.y);
        float* o = out + (size_t)(b * A_N + i) * 6;
        o[0] = bx.x; o[1] = bx.y; o[2] = bx.z; o[3] = bx.w; o[4] = p;
        if (!(p > 0.5f)) atomicOr(&sup[i >> 5], 1u << (i & 31));
    }
    __syncthreads();

    // greedy NMS: serial over survivors, parallel over candidates
    for (;;) {
        if (tid == 0) {
            int i = s_cur + 1;
            while (i < A_N && ((sup[i >> 5] >> (i & 31)) & 1u)) i++;
            s_cur = i;
        }
        __syncthreads();
        int cur = s_cur;
        if (cur >= A_N) break;
        float4 bi = sbox[cur];
        float ai = sarea[cur];
        for (int a = tid; a < A_N; a += 1024) {
            if (a == cur) continue;
            if ((sup[a >> 5] >> (a & 31)) & 1u) continue;
            float4 bj = sbox[a];
            float iw = fminf(bi.z, bj.z) - fmaxf(bi.x, bj.x);
            float ih = fminf(bi.w, bj.w) - fmaxf(bi.y, bj.y);
            if (iw > 0.f && ih > 0.f) {
                float inter = iw * ih;
                float ov = inter / (ai + sarea[a] - inter);
                if (ov > 0.5f) atomicOr(&sup[a >> 5], 1u << (a & 31));
            }
        }
        __syncthreads();
    }

    for (int i = tid; i < A_N; i += 1024)
        out[(size_t)(b * A_N + i) * 6 + 5] = ((sup[i >> 5] >> (i & 31)) & 1u) ? 0.f : 1.f;
}

// ---------------- launch ----------------------------------------------------
extern "C" void kernel_launch(void* const* d_in, const int* in_sizes, int n_in,
                              void* d_out, int out_size) {
    const float* x      = (const float*)d_in[0];
    const float* conv_w = (const float*)d_in[1];
    const float* conv_b = (const float*)d_in[2];
    const float* reg_w  = (const float*)d_in[3];
    const float* reg_b  = (const float*)d_in[4];
    const float* cls_w  = (const float*)d_in[5];
    const float* cls_b  = (const float*)d_in[6];
    const float* anchors = (const float*)d_in[7];
    float* out = (float*)d_out;

    transpose_w<<<dim3(K_TOT / 32, N_TOT / 32), dim3(32, 32)>>>(conv_w);
    im2col_k<<<(M_TOT * K_TOT + 255) / 256, 256>>>(x);
    conv_gemm64<<<dim3(20, 8), 256>>>(conv_b);
    heads_decode<<<M_TOT, 128>>>(reg_w, reg_b, cls_w, cls_b, anchors);

    cudaFuncSetAttribute(sort_nms, cudaFuncAttributeMaxDynamicSharedMemorySize, SMEM_NMS_BYTES);
    sort_nms<<<2, 1024, SMEM_NMS_BYTES>>>(out);
}

// round 3
// speedup vs baseline: 7.4797x; 7.4797x over previous
#include <cuda_runtime.h>

#define A_N 5625
#define SORT_N 8192
#define M_TOT 1250
#define K_TOT 4608
#define N_TOT 512
#define KSPLIT 4
#define KCHUNK 1152          // 4608 / 4

// ---------------- scratch (device globals; no runtime allocation) ----------
__device__ float g_A[M_TOT * K_TOT];                    // im2col
__device__ float g_Bt[K_TOT * N_TOT];                   // transposed weights
__device__ float2 g_psum[KSPLIT * M_TOT * N_TOT];       // double-float partials
__device__ float g_h[M_TOT * N_TOT];                    // conv out (fp32-rounded)
__device__ float g_so[M_TOT * 45];                      // head outputs
__device__ float4 g_boxes[2 * A_N];
__device__ float g_probs[2 * A_N];
__device__ unsigned long long g_keys[2 * A_N];

// ---------------- weight transpose: Bt[k][n] = w[n][k] ---------------------
__global__ void transpose_w(const float* __restrict__ w) {
    __shared__ float sh[32][33];
    int k0 = blockIdx.x * 32, n0 = blockIdx.y * 32;
    int tx = threadIdx.x, ty = threadIdx.y;
    sh[ty][tx] = w[(size_t)(n0 + ty) * K_TOT + k0 + tx];
    __syncthreads();
    g_Bt[(size_t)(k0 + ty) * N_TOT + n0 + tx] = sh[tx][ty];
}

// ---------------- im2col with SAME zero padding -----------------------------
__global__ void im2col_k(const float* __restrict__ x) {
    int e = blockIdx.x * 256 + threadIdx.x;
    if (e >= M_TOT * K_TOT) return;
    int m = e / K_TOT, k = e - m * K_TOT;
    int b = m / 625, p = m - b * 625;
    int y = p / 25, xx = p - y * 25;
    int ci = k / 9, r = k - ci * 9;
    int ky = r / 3, kx = r - ky * 3;
    int iy = y + ky - 1, ix = xx + kx - 1;
    float v = 0.f;
    if (iy >= 0 && iy < 25 && ix >= 0 && ix < 25)
        v = x[((size_t)(b * 512 + ci) * 25 + iy) * 25 + ix];
    g_A[e] = v;
}

// ---------------- conv GEMM: compensated fp32 (fast2sum + TwoProdFMA) ------
// 64x64 tile, 256 threads, 4x4 micro, split-K x4. Error ~1e-10.
__global__ void __launch_bounds__(256) conv_gemm_df() {
    __shared__ float As[16][68];
    __shared__ float Bs[16][64];
    int m0 = blockIdx.x * 64;
    int n0 = blockIdx.y * 64;
    int zz = blockIdx.z;
    int kbase = zz * KCHUNK;
    int tid = threadIdx.x;
    int tr = tid >> 4, tc = tid & 15;

    float s[4][4], lo[4][4];
#pragma unroll
    for (int r = 0; r < 4; r++)
#pragma unroll
        for (int c = 0; c < 4; c++) { s[r][c] = 0.f; lo[r][c] = 0.f; }

    int ar = tid >> 2, aq = (tid & 3) * 4;   // A: 64 rows x 16 k
    int bk = tid >> 4, bn = (tid & 15) * 4;  // B: 16 k x 64 n

    const float* Ab = g_A + (size_t)m0 * K_TOT + kbase;
    const float* Bb = g_Bt + (size_t)kbase * N_TOT + n0;
    bool arow_ok = (m0 + ar) < M_TOT;

    for (int k0 = 0; k0 < KCHUNK; k0 += 16) {
        float4 ra = arow_ok ? *(const float4*)(Ab + (size_t)ar * K_TOT + k0 + aq)
                            : make_float4(0.f, 0.f, 0.f, 0.f);
        float4 rb = *(const float4*)(Bb + (size_t)(k0 + bk) * N_TOT + bn);
        __syncthreads();
        As[aq + 0][ar] = ra.x; As[aq + 1][ar] = ra.y;
        As[aq + 2][ar] = ra.z; As[aq + 3][ar] = ra.w;
        *(float4*)&Bs[bk][bn] = rb;
        __syncthreads();

#pragma unroll
        for (int ks = 0; ks < 16; ks++) {
            float4 a = *(float4*)&As[ks][tr * 4];
            float4 b = *(float4*)&Bs[ks][tc * 4];
            float av[4] = {a.x, a.y, a.z, a.w};
            float bv[4] = {b.x, b.y, b.z, b.w};
#pragma unroll
            for (int r = 0; r < 4; r++)
#pragma unroll
                for (int c = 0; c < 4; c++) {
                    float p = av[r] * bv[c];
                    float e = __fmaf_rn(av[r], bv[c], -p);   // exact product tail
                    float t = s[r][c] + p;
                    float z = t - s[r][c];
                    float err = p - z;                        // fast2sum tail
                    s[r][c] = t;
                    lo[r][c] += (err + e);
                }
        }
    }

    float2* Co = g_psum + (size_t)zz * (M_TOT * N_TOT);
#pragma unroll
    for (int r = 0; r < 4; r++) {
        int m = m0 + tr * 4 + r;
        if (m < M_TOT) {
#pragma unroll
            for (int c = 0; c < 4; c++) {
                int n = n0 + tc * 4 + c;
                Co[(size_t)m * N_TOT + n] = make_float2(s[r][c], lo[r][c]);
            }
        }
    }
}

// ---------------- reduce split-K double-float slabs + bias + relu ----------
__global__ void reduce_relu(const float* __restrict__ conv_b) {
    int i = blockIdx.x * 256 + threadIdx.x;
    if (i >= M_TOT * N_TOT) return;
    int n = i & (N_TOT - 1);
    double acc = (double)conv_b[n];
#pragma unroll
    for (int z = 0; z < KSPLIT; z++) {
        float2 v = g_psum[(size_t)z * (M_TOT * N_TOT) + i];
        acc += (double)v.x + (double)v.y;
    }
    g_h[i] = fmaxf((float)acc, 0.f);
}

// ---------------- head dots: one warp per (m, o), compensated fp32 ---------
__global__ void heads_dots(const float* __restrict__ reg_w, const float* __restrict__ reg_b,
                           const float* __restrict__ cls_w, const float* __restrict__ cls_b) {
    int gw = (blockIdx.x * 256 + threadIdx.x) >> 5;
    int lane = threadIdx.x & 31;
    if (gw >= M_TOT * 45) return;
    int m = gw / 45, o = gw - m * 45;
    const float* w = (o < 36) ? (reg_w + (size_t)o * 512) : (cls_w + (size_t)(o - 36) * 512);
    float bias = (o < 36) ? reg_b[o] : cls_b[o - 36];
    const float* hrow = g_h + (size_t)m * 512;
    float s = 0.f, lo = 0.f;
#pragma unroll
    for (int j = 0; j < 16; j++) {
        int idx = lane + 32 * j;
        float a = hrow[idx], b = __ldg(w + idx);
        float p = a * b;
        float e = __fmaf_rn(a, b, -p);
        float t = s + p;
        float z = t - s;
        float err = p - z;
        s = t;
        lo += (err + e);
    }
    double d = (double)s + (double)lo;
#pragma unroll
    for (int off = 16; off > 0; off >>= 1)
        d += __shfl_down_sync(0xffffffffu, d, off);
    if (lane == 0) g_so[gw] = (float)(d + (double)bias);
}

// ---------------- decode boxes + probs + sort keys -------------------------
__global__ void decode_keys(const float* __restrict__ anchors) {
    int i = blockIdx.x * 256 + threadIdx.x;
    if (i >= M_TOT * 9) return;
    int m = i / 9, t9 = i - m * 9;
    const float* so = g_so + (size_t)m * 45;
    int b = m / 625, p = m - b * 625;
    int a = p * 9 + t9;
    float4 anc = ((const float4*)anchors)[a];
    float acx = (anc.x + anc.z) * 0.5f, acy = (anc.y + anc.w) * 0.5f;
    float aw = anc.z - anc.x, ah = anc.w - anc.y;
    float ox = so[t9 * 4 + 0], oy = so[t9 * 4 + 1];
    float ow = so[t9 * 4 + 2], oh = so[t9 * 4 + 3];
    float cx = ox * aw / 10.0f + acx;
    float cy = oy * ah / 10.0f + acy;
    float bw = expf(ow / 5.0f) * aw;
    float bh = expf(oh / 5.0f) * ah;
    float4 box = make_float4(cx - bw * 0.5f, cy - bh * 0.5f, cx + bw * 0.5f, cy + bh * 0.5f);
    float logit = so[36 + t9];
    float prob = 1.0f / (1.0f + expf(-logit));
    int gi = b * A_N + a;
    g_boxes[gi] = box;
    g_probs[gi] = prob;
    float keyf = (prob > 0.5f) ? prob : -1.0f;
    unsigned u = __float_as_uint(keyf);
    u = (u & 0x80000000u) ? ~u : (u | 0x80000000u);
    g_keys[gi] = ((unsigned long long)(~u) << 32) | (unsigned)a;
}

// ---------------- per-image stable sort + greedy NMS -----------------------
#define SMEM_ARR   0
#define SMEM_BOX   65536
#define SMEM_AREA  (65536 + 90112)
#define SMEM_SUP   (65536 + 90112 + 22528)
#define SMEM_NMS_BYTES (SMEM_SUP + 192 * 4)

__global__ void __launch_bounds__(1024) sort_nms(float* __restrict__ out) {
    extern __shared__ unsigned char smem_raw[];
    unsigned long long* arr = (unsigned long long*)(smem_raw + SMEM_ARR);
    float4* sbox = (float4*)(smem_raw + SMEM_BOX);
    float* sarea = (float*)(smem_raw + SMEM_AREA);
    unsigned* sup = (unsigned*)(smem_raw + SMEM_SUP);
    __shared__ int s_cur;

    int b = blockIdx.x;
    int tid = threadIdx.x;

    for (int i = tid; i < SORT_N; i += 1024)
        arr[i] = (i < A_N) ? g_keys[b * A_N + i] : 0xFFFFFFFFFFFFFFFFull;
    if (tid < 192) sup[tid] = 0u;
    if (tid == 0) s_cur = -1;
    __syncthreads();

    for (int k = 2; k <= SORT_N; k <<= 1) {
        for (int j = k >> 1; j > 0; j >>= 1) {
            for (int i = tid; i < SORT_N; i += 1024) {
                int ixj = i ^ j;
                if (ixj > i) {
                    unsigned long long u = arr[i], v = arr[ixj];
                    bool up = (i & k) == 0;
                    if ((u > v) == up) { arr[i] = v; arr[ixj] = u; }
                }
            }
            __syncthreads();
        }
    }

    for (int i = tid; i < A_N; i += 1024) {
        unsigned idx = (unsigned)(arr[i] & 0xFFFFFFFFu);
        float4 bx = g_boxes[b * A_N + idx];
        float p = g_probs[b * A_N + idx];
        sbox[i] = bx;
        sarea[i] = (bx.z - bx.x) * (bx.w - bx.y);
        float* o = out + (size_t)(b * A_N + i) * 6;
        o[0] = bx.x; o[1] = bx.y; o[2] = bx.z; o[3] = bx.w; o[4] = p;
        if (!(p > 0.5f)) atomicOr(&sup[i >> 5], 1u << (i & 31));
    }
    __syncthreads();

    for (;;) {
        if (tid == 0) {
            int i = s_cur + 1;
            while (i < A_N && ((sup[i >> 5] >> (i & 31)) & 1u)) i++;
            s_cur = i;
        }
        __syncthreads();
        int cur = s_cur;
        if (cur >= A_N) break;
        float4 bi = sbox[cur];
        float ai = sarea[cur];
        for (int a = tid; a < A_N; a += 1024) {
            if (a == cur) continue;
            if ((sup[a >> 5] >> (a & 31)) & 1u) continue;
            float4 bj = sbox[a];
            float iw = fminf(bi.z, bj.z) - fmaxf(bi.x, bj.x);
            float ih = fminf(bi.w, bj.w) - fmaxf(bi.y, bj.y);
            if (iw > 0.f && ih > 0.f) {
                float inter = iw * ih;
                float ov = inter / (ai + sarea[a] - inter);
                if (ov > 0.5f) atomicOr(&sup[a >> 5], 1u << (a & 31));
            }
        }
        __syncthreads();
    }

    for (int i = tid; i < A_N; i += 1024)
        out[(size_t)(b * A_N + i) * 6 + 5] = ((sup[i >> 5] >> (i & 31)) & 1u) ? 0.f : 1.f;
}

// ---------------- launch ----------------------------------------------------
extern "C" void kernel_launch(void* const* d_in, const int* in_sizes, int n_in,
                              void* d_out, int out_size) {
    const float* x      = (const float*)d_in[0];
    const float* conv_w = (const float*)d_in[1];
    const float* conv_b = (const float*)d_in[2];
    const float* reg_w  = (const float*)d_in[3];
    const float* reg_b  = (const float*)d_in[4];
    const float* cls_w  = (const float*)d_in[5];
    const float* cls_b  = (const float*)d_in[6];
    const float* anchors = (const float*)d_in[7];
    float* out = (float*)d_out;

    transpose_w<<<dim3(K_TOT / 32, N_TOT / 32), dim3(32, 32)>>>(conv_w);
    im2col_k<<<(M_TOT * K_TOT + 255) / 256, 256>>>(x);
    conv_gemm_df<<<dim3(20, 8, KSPLIT), 256>>>();
    reduce_relu<<<(M_TOT * N_TOT + 255) / 256, 256>>>(conv_b);
    heads_dots<<<(M_TOT * 45 * 32 + 255) / 256, 256>>>(reg_w, reg_b, cls_w, cls_b);
    decode_keys<<<(M_TOT * 9 + 255) / 256, 256>>>(anchors);

    cudaFuncSetAttribute(sort_nms, cudaFuncAttributeMaxDynamicSharedMemorySize, SMEM_NMS_BYTES);
    sort_nms<<<2, 1024, SMEM_NMS_BYTES>>>(out);
}

// round 4
// speedup vs baseline: 7.7435x; 1.0353x over previous
#include <cuda_runtime.h>

#define A_N 5625
#define SORT_N 8192
#define M_TOT 1250
#define K_TOT 4608
#define N_TOT 512
#define KSPLIT 8
#define KCHUNK 576           // 4608 / 8

typedef unsigned long long u64;

// ---------------- scratch (device globals; no runtime allocation) ----------
__device__ float g_A[M_TOT * K_TOT];                    // im2col
__device__ float g_Bt[K_TOT * N_TOT];                   // transposed weights
__device__ float2 g_psum[KSPLIT * M_TOT * N_TOT];       // double-float partials
__device__ float g_h[M_TOT * N_TOT];                    // conv out (fp32-rounded)
__device__ float g_so[M_TOT * 45];                      // head outputs
__device__ float4 g_boxes[2 * A_N];
__device__ float g_probs[2 * A_N];
__device__ u64 g_keys[2 * A_N];

// ---------------- packed f32x2 helpers --------------------------------------
__device__ __forceinline__ u64 f2mul(u64 a, u64 b) {
    u64 d; asm("mul.rn.f32x2 %0, %1, %2;" : "=l"(d) : "l"(a), "l"(b)); return d;
}
__device__ __forceinline__ u64 f2fma(u64 a, u64 b, u64 c) {
    u64 d; asm("fma.rn.f32x2 %0, %1, %2, %3;" : "=l"(d) : "l"(a), "l"(b), "l"(c)); return d;
}
__device__ __forceinline__ u64 f2add(u64 a, u64 b) {
    u64 d; asm("add.rn.f32x2 %0, %1, %2;" : "=l"(d) : "l"(a), "l"(b)); return d;
}
__device__ __forceinline__ u64 f2dup(float x) {
    u64 d; unsigned u = __float_as_uint(x);
    asm("mov.b64 %0, {%1, %1};" : "=l"(d) : "r"(u)); return d;
}

// ---------------- weight transpose: Bt[k][n] = w[n][k] ---------------------
__global__ void transpose_w(const float* __restrict__ w) {
    __shared__ float sh[32][33];
    int k0 = blockIdx.x * 32, n0 = blockIdx.y * 32;
    int tx = threadIdx.x, ty = threadIdx.y;
    sh[ty][tx] = w[(size_t)(n0 + ty) * K_TOT + k0 + tx];
    __syncthreads();
    g_Bt[(size_t)(k0 + ty) * N_TOT + n0 + tx] = sh[tx][ty];
}

// ---------------- im2col with SAME zero padding -----------------------------
__global__ void im2col_k(const float* __restrict__ x) {
    int e = blockIdx.x * 256 + threadIdx.x;
    if (e >= M_TOT * K_TOT) return;
    int m = e / K_TOT, k = e - m * K_TOT;
    int b = m / 625, p = m - b * 625;
    int y = p / 25, xx = p - y * 25;
    int ci = k / 9, r = k - ci * 9;
    int ky = r / 3, kx = r - ky * 3;
    int iy = y + ky - 1, ix = xx + kx - 1;
    float v = 0.f;
    if (iy >= 0 && iy < 25 && ix >= 0 && ix < 25)
        v = x[((size_t)(b * 512 + ci) * 25 + iy) * 25 + ix];
    g_A[e] = v;
}

// ---------------- conv GEMM: compensated fp32 on packed f32x2 --------------
// 64x64 tile, 256 threads, 4x4 micro (2 row-pairs), split-K x8.
// Per-lane math identical to scalar (mul, fma, fast2sum) -> error ~1e-10.
__global__ void __launch_bounds__(256) conv_gemm_df2() {
    __shared__ float As[16][68];
    __shared__ float Bs[16][64];
    int m0 = blockIdx.x * 64;
    int n0 = blockIdx.y * 64;
    int zz = blockIdx.z;
    int kbase = zz * KCHUNK;
    int tid = threadIdx.x;
    int tr = tid >> 4, tc = tid & 15;

    const u64 M1 = f2dup(-1.0f);
    u64 s[2][4], lo[2][4];
#pragma unroll
    for (int i = 0; i < 2; i++)
#pragma unroll
        for (int c = 0; c < 4; c++) { s[i][c] = 0ull; lo[i][c] = 0ull; }

    int ar = tid >> 2, aq = (tid & 3) * 4;   // A: 64 rows x 16 k
    int bk = tid >> 4, bn = (tid & 15) * 4;  // B: 16 k x 64 n

    const float* Ab = g_A + (size_t)m0 * K_TOT + kbase;
    const float* Bb = g_Bt + (size_t)kbase * N_TOT + n0;
    bool arow_ok = (m0 + ar) < M_TOT;

    for (int k0 = 0; k0 < KCHUNK; k0 += 16) {
        float4 ra = arow_ok ? *(const float4*)(Ab + (size_t)ar * K_TOT + k0 + aq)
                            : make_float4(0.f, 0.f, 0.f, 0.f);
        float4 rb = *(const float4*)(Bb + (size_t)(k0 + bk) * N_TOT + bn);
        __syncthreads();
        As[aq + 0][ar] = ra.x; As[aq + 1][ar] = ra.y;
        As[aq + 2][ar] = ra.z; As[aq + 3][ar] = ra.w;
        *(float4*)&Bs[bk][bn] = rb;
        __syncthreads();

#pragma unroll
        for (int ks = 0; ks < 16; ks++) {
            // a pairs: lane0 = row tr*4+0/2, lane1 = row tr*4+1/3
            u64 a01 = *(const u64*)&As[ks][tr * 4];
            u64 a23 = *(const u64*)&As[ks][tr * 4 + 2];
            u64 na01 = f2mul(a01, M1);
            u64 na23 = f2mul(a23, M1);
            float4 bf = *(float4*)&Bs[ks][tc * 4];
            float bv[4] = {bf.x, bf.y, bf.z, bf.w};
#pragma unroll
            for (int c = 0; c < 4; c++) {
                u64 bb = f2dup(bv[c]);
#pragma unroll
                for (int i = 0; i < 2; i++) {
                    u64 a  = (i == 0) ? a01 : a23;
                    u64 na = (i == 0) ? na01 : na23;
                    u64 np = f2mul(na, bb);          // -p
                    u64 e  = f2fma(a, bb, np);       // exact product tail
                    u64 t  = f2fma(np, M1, s[i][c]); // s + p
                    u64 z  = f2fma(s[i][c], M1, t);  // t - s
                    u64 q  = f2add(np, z);           // -(p - z) = -err
                    lo[i][c] = f2fma(q, M1, lo[i][c]); // lo + err
                    lo[i][c] = f2add(lo[i][c], e);
                    s[i][c] = t;
                }
            }
        }
    }

    float2* Co = g_psum + (size_t)zz * (M_TOT * N_TOT);
#pragma unroll
    for (int i = 0; i < 2; i++)
#pragma unroll
        for (int lane = 0; lane < 2; lane++) {
            int m = m0 + tr * 4 + i * 2 + lane;
            if (m < M_TOT) {
#pragma unroll
                for (int c = 0; c < 4; c++) {
                    int n = n0 + tc * 4 + c;
                    unsigned shi = (lane == 0) ? (unsigned)(s[i][c] & 0xffffffffu)
                                               : (unsigned)(s[i][c] >> 32);
                    unsigned slo = (lane == 0) ? (unsigned)(lo[i][c] & 0xffffffffu)
                                               : (unsigned)(lo[i][c] >> 32);
                    Co[(size_t)m * N_TOT + n] =
                        make_float2(__uint_as_float(shi), __uint_as_float(slo));
                }
            }
        }
}

// ---------------- reduce split-K double-float slabs + bias + relu ----------
__global__ void reduce_relu(const float* __restrict__ conv_b) {
    int i = blockIdx.x * 256 + threadIdx.x;
    if (i >= M_TOT * N_TOT) return;
    int n = i & (N_TOT - 1);
    double acc = (double)conv_b[n];
#pragma unroll
    for (int z = 0; z < KSPLIT; z++) {
        float2 v = g_psum[(size_t)z * (M_TOT * N_TOT) + i];
        acc += (double)v.x + (double)v.y;
    }
    g_h[i] = fmaxf((float)acc, 0.f);
}

// ---------------- head dots: one warp per (m, o), compensated fp32 ---------
__global__ void heads_dots(const float* __restrict__ reg_w, const float* __restrict__ reg_b,
                           const float* __restrict__ cls_w, const float* __restrict__ cls_b) {
    int gw = (blockIdx.x * 256 + threadIdx.x) >> 5;
    int lane = threadIdx.x & 31;
    if (gw >= M_TOT * 45) return;
    int m = gw / 45, o = gw - m * 45;
    const float* w = (o < 36) ? (reg_w + (size_t)o * 512) : (cls_w + (size_t)(o - 36) * 512);
    float bias = (o < 36) ? reg_b[o] : cls_b[o - 36];
    const float* hrow = g_h + (size_t)m * 512;
    float s = 0.f, lo = 0.f;
#pragma unroll
    for (int j = 0; j < 16; j++) {
        int idx = lane + 32 * j;
        float a = hrow[idx], b = __ldg(w + idx);
        float p = a * b;
        float e = __fmaf_rn(a, b, -p);
        float t = s + p;
        float z = t - s;
        float err = p - z;
        s = t;
        lo += (err + e);
    }
    double d = (double)s + (double)lo;
#pragma unroll
    for (int off = 16; off > 0; off >>= 1)
        d += __shfl_down_sync(0xffffffffu, d, off);
    if (lane == 0) g_so[gw] = (float)(d + (double)bias);
}

// ---------------- decode boxes + probs + sort keys -------------------------
__global__ void decode_keys(const float* __restrict__ anchors) {
    int i = blockIdx.x * 256 + threadIdx.x;
    if (i >= M_TOT * 9) return;
    int m = i / 9, t9 = i - m * 9;
    const float* so = g_so + (size_t)m * 45;
    int b = m / 625, p = m - b * 625;
    int a = p * 9 + t9;
    float4 anc = ((const float4*)anchors)[a];
    float acx = (anc.x + anc.z) * 0.5f, acy = (anc.y + anc.w) * 0.5f;
    float aw = anc.z - anc.x, ah = anc.w - anc.y;
    float ox = so[t9 * 4 + 0], oy = so[t9 * 4 + 1];
    float ow = so[t9 * 4 + 2], oh = so[t9 * 4 + 3];
    float cx = ox * aw / 10.0f + acx;
    float cy = oy * ah / 10.0f + acy;
    float bw = expf(ow / 5.0f) * aw;
    float bh = expf(oh / 5.0f) * ah;
    float4 box = make_float4(cx - bw * 0.5f, cy - bh * 0.5f, cx + bw * 0.5f, cy + bh * 0.5f);
    float logit = so[36 + t9];
    float prob = 1.0f / (1.0f + expf(-logit));
    int gi = b * A_N + a;
    g_boxes[gi] = box;
    g_probs[gi] = prob;
    float keyf = (prob > 0.5f) ? prob : -1.0f;
    unsigned u = __float_as_uint(keyf);
    u = (u & 0x80000000u) ? ~u : (u | 0x80000000u);
    g_keys[gi] = ((u64)(~u) << 32) | (unsigned)a;
}

// ---------------- per-image stable sort + greedy NMS -----------------------
#define SMEM_ARR   0
#define SMEM_BOX   65536
#define SMEM_AREA  (65536 + 90112)
#define SMEM_SUP   (65536 + 90112 + 22528)
#define SMEM_NMS_BYTES (SMEM_SUP + 192 * 4)

__global__ void __launch_bounds__(1024) sort_nms(float* __restrict__ out) {
    extern __shared__ unsigned char smem_raw[];
    u64* arr = (u64*)(smem_raw + SMEM_ARR);
    float4* sbox = (float4*)(smem_raw + SMEM_BOX);
    float* sarea = (float*)(smem_raw + SMEM_AREA);
    unsigned* sup = (unsigned*)(smem_raw + SMEM_SUP);
    __shared__ int s_cur;

    int b = blockIdx.x;
    int tid = threadIdx.x;

    for (int i = tid; i < SORT_N; i += 1024)
        arr[i] = (i < A_N) ? g_keys[b * A_N + i] : 0xFFFFFFFFFFFFFFFFull;
    if (tid < 192) sup[tid] = 0u;
    if (tid == 0) s_cur = -1;
    __syncthreads();

    for (int k = 2; k <= SORT_N; k <<= 1) {
        for (int j = k >> 1; j > 0; j >>= 1) {
            for (int i = tid; i < SORT_N; i += 1024) {
                int ixj = i ^ j;
                if (ixj > i) {
                    u64 u = arr[i], v = arr[ixj];
                    bool up = (i & k) == 0;
                    if ((u > v) == up) { arr[i] = v; arr[ixj] = u; }
                }
            }
            __syncthreads();
        }
    }

    for (int i = tid; i < A_N; i += 1024) {
        unsigned idx = (unsigned)(arr[i] & 0xFFFFFFFFu);
        float4 bx = g_boxes[b * A_N + idx];
        float p = g_probs[b * A_N + idx];
        sbox[i] = bx;
        sarea[i] = (bx.z - bx.x) * (bx.w - bx.y);
        float* o = out + (size_t)(b * A_N + i) * 6;
        o[0] = bx.x; o[1] = bx.y; o[2] = bx.z; o[3] = bx.w; o[4] = p;
        if (!(p > 0.5f)) atomicOr(&sup[i >> 5], 1u << (i & 31));
    }
    __syncthreads();

    for (;;) {
        if (tid == 0) {
            int i = s_cur + 1;
            while (i < A_N && ((sup[i >> 5] >> (i & 31)) & 1u)) i++;
            s_cur = i;
        }
        __syncthreads();
        int cur = s_cur;
        if (cur >= A_N) break;
        float4 bi = sbox[cur];
        float ai = sarea[cur];
        for (int a = tid; a < A_N; a += 1024) {
            if (a == cur) continue;
            if ((sup[a >> 5] >> (a & 31)) & 1u) continue;
            float4 bj = sbox[a];
            float iw = fminf(bi.z, bj.z) - fmaxf(bi.x, bj.x);
            float ih = fminf(bi.w, bj.w) - fmaxf(bi.y, bj.y);
            if (iw > 0.f && ih > 0.f) {
                float inter = iw * ih;
                float ov = inter / (ai + sarea[a] - inter);
                if (ov > 0.5f) atomicOr(&sup[a >> 5], 1u << (a & 31));
            }
        }
        __syncthreads();
    }

    for (int i = tid; i < A_N; i += 1024)
        out[(size_t)(b * A_N + i) * 6 + 5] = ((sup[i >> 5] >> (i & 31)) & 1u) ? 0.f : 1.f;
}

// ---------------- launch ----------------------------------------------------
extern "C" void kernel_launch(void* const* d_in, const int* in_sizes, int n_in,
                              void* d_out, int out_size) {
    const float* x      = (const float*)d_in[0];
    const float* conv_w = (const float*)d_in[1];
    const float* conv_b = (const float*)d_in[2];
    const float* reg_w  = (const float*)d_in[3];
    const float* reg_b  = (const float*)d_in[4];
    const float* cls_w  = (const float*)d_in[5];
    const float* cls_b  = (const float*)d_in[6];
    const float* anchors = (const float*)d_in[7];
    float* out = (float*)d_out;

    transpose_w<<<dim3(K_TOT / 32, N_TOT / 32), dim3(32, 32)>>>(conv_w);
    im2col_k<<<(M_TOT * K_TOT + 255) / 256, 256>>>(x);
    conv_gemm_df2<<<dim3(20, 8, KSPLIT), 256>>>();
    reduce_relu<<<(M_TOT * N_TOT + 255) / 256, 256>>>(conv_b);
    heads_dots<<<(M_TOT * 45 * 32 + 255) / 256, 256>>>(reg_w, reg_b, cls_w, cls_b);
    decode_keys<<<(M_TOT * 9 + 255) / 256, 256>>>(anchors);

    cudaFuncSetAttribute(sort_nms, cudaFuncAttributeMaxDynamicSharedMemorySize, SMEM_NMS_BYTES);
    sort_nms<<<2, 1024, SMEM_NMS_BYTES>>>(out);
}

// round 5
// speedup vs baseline: 9.3058x; 1.2017x over previous
#include <cuda_runtime.h>

#define A_N 5625
#define SORT_N 8192
#define M_TOT 1250
#define K_TOT 4608
#define N_TOT 512
#define KSPLIT 8
#define KCHUNK 576           // 4608 / 8
#define NW 88                // mask words per row (88*64 = 5632 >= 5625)

typedef unsigned long long u64;

// ---------------- scratch (device globals; no runtime allocation) ----------
__device__ float g_A[M_TOT * K_TOT];
__device__ float g_Bt[K_TOT * N_TOT];
__device__ float2 g_psum[KSPLIT * M_TOT * N_TOT];
__device__ float g_h[M_TOT * N_TOT];
__device__ float g_so[M_TOT * 45];
__device__ float4 g_boxes[2 * A_N];
__device__ float g_probs[2 * A_N];
__device__ u64 g_keys[2 * A_N];
__device__ float4 g_sbox[2 * A_N];                  // sorted boxes
__device__ int g_nvalid[2];
__device__ u64 g_nmsmask[2 * A_N * NW];             // IoU>0.5 bit matrix, 7.9 MB

// ---------------- weight transpose: Bt[k][n] = w[n][k] ---------------------
__global__ void transpose_w(const float* __restrict__ w) {
    __shared__ float sh[32][33];
    int k0 = blockIdx.x * 32, n0 = blockIdx.y * 32;
    int tx = threadIdx.x, ty = threadIdx.y;
    sh[ty][tx] = w[(size_t)(n0 + ty) * K_TOT + k0 + tx];
    __syncthreads();
    g_Bt[(size_t)(k0 + ty) * N_TOT + n0 + tx] = sh[tx][ty];
}

// ---------------- im2col with SAME zero padding -----------------------------
__global__ void im2col_k(const float* __restrict__ x) {
    int e = blockIdx.x * 256 + threadIdx.x;
    if (e >= M_TOT * K_TOT) return;
    int m = e / K_TOT, k = e - m * K_TOT;
    int b = m / 625, p = m - b * 625;
    int y = p / 25, xx = p - y * 25;
    int ci = k / 9, r = k - ci * 9;
    int ky = r / 3, kx = r - ky * 3;
    int iy = y + ky - 1, ix = xx + kx - 1;
    float v = 0.f;
    if (iy >= 0 && iy < 25 && ix >= 0 && ix < 25)
        v = x[((size_t)(b * 512 + ci) * 25 + iy) * 25 + ix];
    g_A[e] = v;
}

// ---------------- conv GEMM: compensated fp32 (fast2sum + TwoProdFMA) ------
__global__ void __launch_bounds__(256) conv_gemm_df() {
    __shared__ float As[16][68];
    __shared__ float Bs[16][64];
    int m0 = blockIdx.x * 64;
    int n0 = blockIdx.y * 64;
    int zz = blockIdx.z;
    int kbase = zz * KCHUNK;
    int tid = threadIdx.x;
    int tr = tid >> 4, tc = tid & 15;

    float s[4][4], lo[4][4];
#pragma unroll
    for (int r = 0; r < 4; r++)
#pragma unroll
        for (int c = 0; c < 4; c++) { s[r][c] = 0.f; lo[r][c] = 0.f; }

    int ar = tid >> 2, aq = (tid & 3) * 4;
    int bk = tid >> 4, bn = (tid & 15) * 4;

    const float* Ab = g_A + (size_t)m0 * K_TOT + kbase;
    const float* Bb = g_Bt + (size_t)kbase * N_TOT + n0;
    bool arow_ok = (m0 + ar) < M_TOT;

    for (int k0 = 0; k0 < KCHUNK; k0 += 16) {
        float4 ra = arow_ok ? *(const float4*)(Ab + (size_t)ar * K_TOT + k0 + aq)
                            : make_float4(0.f, 0.f, 0.f, 0.f);
        float4 rb = *(const float4*)(Bb + (size_t)(k0 + bk) * N_TOT + bn);
        __syncthreads();
        As[aq + 0][ar] = ra.x; As[aq + 1][ar] = ra.y;
        As[aq + 2][ar] = ra.z; As[aq + 3][ar] = ra.w;
        *(float4*)&Bs[bk][bn] = rb;
        __syncthreads();

#pragma unroll
        for (int ks = 0; ks < 16; ks++) {
            float4 a = *(float4*)&As[ks][tr * 4];
            float4 b = *(float4*)&Bs[ks][tc * 4];
            float av[4] = {a.x, a.y, a.z, a.w};
            float bv[4] = {b.x, b.y, b.z, b.w};
#pragma unroll
            for (int r = 0; r < 4; r++)
#pragma unroll
                for (int c = 0; c < 4; c++) {
                    float p = av[r] * bv[c];
                    float e = __fmaf_rn(av[r], bv[c], -p);
                    float t = s[r][c] + p;
                    float z = t - s[r][c];
                    float err = p - z;
                    s[r][c] = t;
                    lo[r][c] += (err + e);
                }
        }
    }

    float2* Co = g_psum + (size_t)zz * (M_TOT * N_TOT);
#pragma unroll
    for (int r = 0; r < 4; r++) {
        int m = m0 + tr * 4 + r;
        if (m < M_TOT) {
#pragma unroll
            for (int c = 0; c < 4; c++) {
                int n = n0 + tc * 4 + c;
                Co[(size_t)m * N_TOT + n] = make_float2(s[r][c], lo[r][c]);
            }
        }
    }
}

// ---------------- reduce split-K double-float slabs + bias + relu ----------
__global__ void reduce_relu(const float* __restrict__ conv_b) {
    int i = blockIdx.x * 256 + threadIdx.x;
    if (i >= M_TOT * N_TOT) return;
    int n = i & (N_TOT - 1);
    double acc = (double)conv_b[n];
#pragma unroll
    for (int z = 0; z < KSPLIT; z++) {
        float2 v = g_psum[(size_t)z * (M_TOT * N_TOT) + i];
        acc += (double)v.x + (double)v.y;
    }
    g_h[i] = fmaxf((float)acc, 0.f);
}

// ---------------- head dots: one warp per (m, o), compensated fp32 ---------
__global__ void heads_dots(const float* __restrict__ reg_w, const float* __restrict__ reg_b,
                           const float* __restrict__ cls_w, const float* __restrict__ cls_b) {
    int gw = (blockIdx.x * 256 + threadIdx.x) >> 5;
    int lane = threadIdx.x & 31;
    if (gw >= M_TOT * 45) return;
    int m = gw / 45, o = gw - m * 45;
    const float* w = (o < 36) ? (reg_w + (size_t)o * 512) : (cls_w + (size_t)(o - 36) * 512);
    float bias = (o < 36) ? reg_b[o] : cls_b[o - 36];
    const float* hrow = g_h + (size_t)m * 512;
    float s = 0.f, lo = 0.f;
#pragma unroll
    for (int j = 0; j < 16; j++) {
        int idx = lane + 32 * j;
        float a = hrow[idx], b = __ldg(w + idx);
        float p = a * b;
        float e = __fmaf_rn(a, b, -p);
        float t = s + p;
        float z = t - s;
        float err = p - z;
        s = t;
        lo += (err + e);
    }
    double d = (double)s + (double)lo;
#pragma unroll
    for (int off = 16; off > 0; off >>= 1)
        d += __shfl_down_sync(0xffffffffu, d, off);
    if (lane == 0) g_so[gw] = (float)(d + (double)bias);
}

// ---------------- decode boxes + probs + sort keys -------------------------
__global__ void decode_keys(const float* __restrict__ anchors) {
    int i = blockIdx.x * 256 + threadIdx.x;
    if (i >= M_TOT * 9) return;
    int m = i / 9, t9 = i - m * 9;
    const float* so = g_so + (size_t)m * 45;
    int b = m / 625, p = m - b * 625;
    int a = p * 9 + t9;
    float4 anc = ((const float4*)anchors)[a];
    float acx = (anc.x + anc.z) * 0.5f, acy = (anc.y + anc.w) * 0.5f;
    float aw = anc.z - anc.x, ah = anc.w - anc.y;
    float ox = so[t9 * 4 + 0], oy = so[t9 * 4 + 1];
    float ow = so[t9 * 4 + 2], oh = so[t9 * 4 + 3];
    float cx = ox * aw / 10.0f + acx;
    float cy = oy * ah / 10.0f + acy;
    float bw = expf(ow / 5.0f) * aw;
    float bh = expf(oh / 5.0f) * ah;
    float4 box = make_float4(cx - bw * 0.5f, cy - bh * 0.5f, cx + bw * 0.5f, cy + bh * 0.5f);
    float logit = so[36 + t9];
    float prob = 1.0f / (1.0f + expf(-logit));
    int gi = b * A_N + a;
    g_boxes[gi] = box;
    g_probs[gi] = prob;
    float keyf = (prob > 0.5f) ? prob : -1.0f;
    unsigned u = __float_as_uint(keyf);
    u = (u & 0x80000000u) ? ~u : (u | 0x80000000u);
    g_keys[gi] = ((u64)(~u) << 32) | (unsigned)a;
}

// ---------------- per-image stable bitonic sort + gather -------------------
// dyn smem: u64 arr[8192] = 64 KB
__global__ void __launch_bounds__(1024) sort_pass(float* __restrict__ out) {
    extern __shared__ u64 arr[];
    int b = blockIdx.x;
    int tid = threadIdx.x;

    if (tid == 0) g_nvalid[b] = 0;          // reset every graph replay
    for (int i = tid; i < SORT_N; i += 1024)
        arr[i] = (i < A_N) ? g_keys[b * A_N + i] : 0xFFFFFFFFFFFFFFFFull;
    __syncthreads();

    for (int k = 2; k <= SORT_N; k <<= 1) {
        for (int j = k >> 1; j > 0; j >>= 1) {
            for (int i = tid; i < SORT_N; i += 1024) {
                int ixj = i ^ j;
                if (ixj > i) {
                    u64 u = arr[i], v = arr[ixj];
                    bool up = (i & k) == 0;
                    if ((u > v) == up) { arr[i] = v; arr[ixj] = u; }
                }
            }
            __syncthreads();
        }
    }

    int cnt = 0;
    for (int i = tid; i < A_N; i += 1024) {
        unsigned idx = (unsigned)(arr[i] & 0xFFFFFFFFu);
        float4 bx = g_boxes[b * A_N + idx];
        float p = g_probs[b * A_N + idx];
        g_sbox[b * A_N + i] = bx;
        float* o = out + (size_t)(b * A_N + i) * 6;
        o[0] = bx.x; o[1] = bx.y; o[2] = bx.z; o[3] = bx.w; o[4] = p;
        if (p > 0.5f) cnt++;
    }
    atomicAdd(&g_nvalid[b], cnt);
}

// ---------------- IoU bit matrix: rows i (valid only) x bits j -------------
// grid (44, 2); CTA = 256 threads = 8 warps, 16 rows per warp; smem = boxes.
__global__ void __launch_bounds__(256) iou_mask() {
    extern __shared__ float4 sb[];          // 5625 sorted boxes
    int b = blockIdx.y;
    int nv = g_nvalid[b];
    int r0 = blockIdx.x * 128;
    if (r0 >= nv) return;
    int tid = threadIdx.x;
    int wid = tid >> 5, lane = tid & 31;

    for (int i = tid; i < A_N; i += 256) sb[i] = g_sbox[b * A_N + i];
    __syncthreads();

#pragma unroll 1
    for (int rr = 0; rr < 16; rr++) {
        int i = r0 + wid * 16 + rr;
        if (i >= nv) continue;
        float4 bi = sb[i];
        float ai = (bi.z - bi.x) * (bi.w - bi.y);
        u64* row = g_nmsmask + ((size_t)b * A_N + i) * NW;
#pragma unroll 1
        for (int w = 0; w < NW; w++) {
            int j0 = w * 64 + lane;
            int j1 = j0 + 32;
            bool p0 = false, p1 = false;
            if (j0 < A_N && j0 != i) {
                float4 bj = sb[j0];
                float iw = fminf(bi.z, bj.z) - fmaxf(bi.x, bj.x);
                float ih = fminf(bi.w, bj.w) - fmaxf(bi.y, bj.y);
                float inter = fmaxf(iw, 0.f) * fmaxf(ih, 0.f);
                float aj = (bj.z - bj.x) * (bj.w - bj.y);
                p0 = inter / (ai + aj - inter) > 0.5f;
            }
            if (j1 < A_N && j1 != i) {
                float4 bj = sb[j1];
                float iw = fminf(bi.z, bj.z) - fmaxf(bi.x, bj.x);
                float ih = fminf(bi.w, bj.w) - fmaxf(bi.y, bj.y);
                float inter = fmaxf(iw, 0.f) * fmaxf(ih, 0.f);
                float aj = (bj.z - bj.x) * (bj.w - bj.y);
                p1 = inter / (ai + aj - inter) > 0.5f;
            }
            unsigned m0 = __ballot_sync(0xffffffffu, p0);
            unsigned m1 = __ballot_sync(0xffffffffu, p1);
            if (lane == 0) row[w] = (u64)m0 | ((u64)m1 << 32);
        }
    }
}

// ---------------- serial greedy scan: one warp per image -------------------
#define PF 8
__global__ void __launch_bounds__(32) nms_scan(float* __restrict__ out) {
    int b = blockIdx.x;
    int lane = threadIdx.x;
    int nv = g_nvalid[b];
    const u64* base = g_nmsmask + (size_t)b * A_N * NW;

    int w0 = lane, w1 = lane + 32, w2 = lane + 64;
    bool has2 = w2 < NW;
    u64 rm0 = 0, rm1 = 0, rm2 = 0;

    u64 buf[PF][3];
#pragma unroll
    for (int d = 0; d < PF; d++) {
        if (d < nv) {
            const u64* r = base + (size_t)d * NW;
            buf[d][0] = __ldg(r + w0);
            buf[d][1] = __ldg(r + w1);
            buf[d][2] = has2 ? __ldg(r + w2) : 0ull;
        } else { buf[d][0] = buf[d][1] = buf[d][2] = 0ull; }
    }

    for (int i0 = 0; i0 < nv; i0 += PF) {
#pragma unroll
        for (int d = 0; d < PF; d++) {
            int i = i0 + d;
            if (i >= nv) break;
            u64 c0 = buf[d][0], c1 = buf[d][1], c2 = buf[d][2];
            int ip = i + PF;
            if (ip < nv) {
                const u64* r = base + (size_t)ip * NW;
                buf[d][0] = __ldg(r + w0);
                buf[d][1] = __ldg(r + w1);
                buf[d][2] = has2 ? __ldg(r + w2) : 0ull;
            }
            int w = i >> 6;
            int owner = w & 31, slot = w >> 5;
            u64 myw = (slot == 0) ? rm0 : ((slot == 1) ? rm1 : rm2);
            u64 vw = __shfl_sync(0xffffffffu, myw, owner);
            if (!((vw >> (i & 63)) & 1ull)) {
                rm0 |= c0; rm1 |= c1; if (has2) rm2 |= c2;
            }
        }
    }

    // write keep flags for owned words
#pragma unroll
    for (int s = 0; s < 3; s++) {
        int w = lane + 32 * s;
        if (w >= NW) break;
        u64 r = (s == 0) ? rm0 : ((s == 1) ? rm1 : rm2);
        for (int t = 0; t < 64; t++) {
            int i = w * 64 + t;
            if (i < A_N)
                out[(size_t)(b * A_N + i) * 6 + 5] =
                    (i < nv && !((r >> t) & 1ull)) ? 1.f : 0.f;
        }
    }
}

// ---------------- launch ----------------------------------------------------
extern "C" void kernel_launch(void* const* d_in, const int* in_sizes, int n_in,
                              void* d_out, int out_size) {
    const float* x      = (const float*)d_in[0];
    const float* conv_w = (const float*)d_in[1];
    const float* conv_b = (const float*)d_in[2];
    const float* reg_w  = (const float*)d_in[3];
    const float* reg_b  = (const float*)d_in[4];
    const float* cls_w  = (const float*)d_in[5];
    const float* cls_b  = (const float*)d_in[6];
    const float* anchors = (const float*)d_in[7];
    float* out = (float*)d_out;

    transpose_w<<<dim3(K_TOT / 32, N_TOT / 32), dim3(32, 32)>>>(conv_w);
    im2col_k<<<(M_TOT * K_TOT + 255) / 256, 256>>>(x);
    conv_gemm_df<<<dim3(20, 8, KSPLIT), 256>>>();
    reduce_relu<<<(M_TOT * N_TOT + 255) / 256, 256>>>(conv_b);
    heads_dots<<<(M_TOT * 45 * 32 + 255) / 256, 256>>>(reg_w, reg_b, cls_w, cls_b);
    decode_keys<<<(M_TOT * 9 + 255) / 256, 256>>>(anchors);

    static int attr_done = 0;
    if (!attr_done) {
        cudaFuncSetAttribute(sort_pass, cudaFuncAttributeMaxDynamicSharedMemorySize, SORT_N * 8);
        cudaFuncSetAttribute(iou_mask, cudaFuncAttributeMaxDynamicSharedMemorySize, A_N * 16);
        attr_done = 1;
    }
    sort_pass<<<2, 1024, SORT_N * 8>>>(out);
    iou_mask<<<dim3(44, 2), 256, A_N * 16>>>();
    nms_scan<<<2, 32>>>(out);
}